// round 11
// baseline (speedup 1.0000x reference)
#include <cuda_runtime.h>
#include <cstdint>

#define T_STEPS 512
#define BATCH   64
#define DIN     128
#define DH      1024
#define DOUT    256
#define RANK    64

#define CL      4            // cluster size (CTAs per batch-pair)
#define COLS    256          // DH / CL columns per CTA
#define BGRP    2            // batch elements per cluster (= 2 chains)
// grid = 128 CTAs = 32 clusters * 4; one wave on 148 SMs

// ---------------- C[m,n] = bias[n] + sum_k A[m,k]*B[n,k] --------------------
// A: [M,K] row-major, B: [N,K] row-major (B^T GEMM). Tiles 64x64, BK=32.
__global__ void __launch_bounds__(256) gemm_bt(const float* __restrict__ A,
                                               const float* __restrict__ Bm,
                                               const float* __restrict__ bias,
                                               float* __restrict__ C,
                                               int N, int K) {
    __shared__ float sA[32][68];
    __shared__ float sB[32][68];
    const int tid = threadIdx.x;
    const int m0 = blockIdx.x * 64;
    const int n0 = blockIdx.y * 64;
    const int tx = tid & 15;
    const int ty = tid >> 4;
    const int lrow = tid >> 2;
    const int lkk  = (tid & 3) * 8;

    float acc[4][4];
#pragma unroll
    for (int i = 0; i < 4; i++)
#pragma unroll
        for (int j = 0; j < 4; j++) acc[i][j] = 0.0f;

    for (int k0 = 0; k0 < K; k0 += 32) {
        const float* ap = A + (size_t)(m0 + lrow) * K + k0 + lkk;
        const float* bp = Bm + (size_t)(n0 + lrow) * K + k0 + lkk;
        float4 a0 = *(const float4*)ap;
        float4 a1 = *(const float4*)(ap + 4);
        float4 b0 = *(const float4*)bp;
        float4 b1 = *(const float4*)(bp + 4);
        sA[lkk + 0][lrow] = a0.x; sA[lkk + 1][lrow] = a0.y;
        sA[lkk + 2][lrow] = a0.z; sA[lkk + 3][lrow] = a0.w;
        sA[lkk + 4][lrow] = a1.x; sA[lkk + 5][lrow] = a1.y;
        sA[lkk + 6][lrow] = a1.z; sA[lkk + 7][lrow] = a1.w;
        sB[lkk + 0][lrow] = b0.x; sB[lkk + 1][lrow] = b0.y;
        sB[lkk + 2][lrow] = b0.z; sB[lkk + 3][lrow] = b0.w;
        sB[lkk + 4][lrow] = b1.x; sB[lkk + 5][lrow] = b1.y;
        sB[lkk + 6][lrow] = b1.z; sB[lkk + 7][lrow] = b1.w;
        __syncthreads();
#pragma unroll
        for (int k = 0; k < 32; k++) {
            float4 av = *(const float4*)&sA[k][ty * 4];
            float4 bv = *(const float4*)&sB[k][tx * 4];
            float a[4] = {av.x, av.y, av.z, av.w};
            float b[4] = {bv.x, bv.y, bv.z, bv.w};
#pragma unroll
            for (int i = 0; i < 4; i++)
#pragma unroll
                for (int j = 0; j < 4; j++) acc[i][j] += a[i] * b[j];
        }
        __syncthreads();
    }

    float4 bias4 = *(const float4*)&bias[n0 + tx * 4];
    float bb[4] = {bias4.x, bias4.y, bias4.z, bias4.w};
#pragma unroll
    for (int i = 0; i < 4; i++) {
        float4 o;
        o.x = acc[i][0] + bb[0];
        o.y = acc[i][1] + bb[1];
        o.z = acc[i][2] + bb[2];
        o.w = acc[i][3] + bb[3];
        *(float4*)&C[(size_t)(m0 + ty * 4 + i) * N + n0 + tx * 4] = o;
    }
}

// ---------------- clustered recurrence: dual interleaved chains --------------
__device__ __forceinline__ uint32_t smem_u32(const void* p) {
    uint32_t a;
    asm("{ .reg .u64 t; cvta.to.shared.u64 t, %1; cvt.u32.u64 %0, t; }"
        : "=r"(a) : "l"(p));
    return a;
}

__device__ __forceinline__ void mbar_wait(uint32_t mbar, uint32_t parity) {
    asm volatile(
        "{\n\t"
        ".reg .pred P;\n\t"
        "W%=:\n\t"
        "mbarrier.try_wait.parity.acquire.cta.shared::cta.b64 P, [%0], %1, 0x989680;\n\t"
        "@P bra D%=;\n\t"
        "bra W%=;\n\t"
        "D%=:\n\t"
        "}"
        :: "r"(mbar), "r"(parity) : "memory");
}

__global__ void __launch_bounds__(256, 1) __cluster_dims__(CL, 1, 1)
rnn_recur(const float* __restrict__ U, const float* __restrict__ V,
          float* __restrict__ hidden) {
    // [chain][parity][srcRankCTA][r]
    __shared__ __align__(16) float pbuf[2][2][CL][RANK];
    __shared__ __align__(16) float pcur[2][RANK];
    __shared__ __align__(16) float sH[2][COLS];
    __shared__ __align__(16) float sTmp[2][CL][RANK];
    __shared__ __align__(8) unsigned long long mbar[2];

    const int tid  = threadIdx.x;
    const int rank = blockIdx.x & (CL - 1);
    const int clus = blockIdx.x >> 2;
    const int b0   = clus * BGRP;
    const int colbase = rank * COLS;
    const int col  = colbase + tid;

    const int rr = tid & 63;                    // phase iii: rank index
    const int qq = tid >> 6;                    // phase iii: 64-col chunk

    // ---- persistent register weights (shared by both chains) ----
    float u[RANK];
#pragma unroll
    for (int r = 0; r < RANK; r += 4) {
        float4 t4 = *(const float4*)&U[(size_t)col * RANK + r];
        u[r] = t4.x; u[r + 1] = t4.y; u[r + 2] = t4.z; u[r + 3] = t4.w;
    }
    float v[64];
#pragma unroll
    for (int j = 0; j < 64; j += 4) {
        float4 t4 = *(const float4*)&V[(size_t)rr * DH + colbase + qq * 64 + j];
        v[j] = t4.x; v[j + 1] = t4.y; v[j + 2] = t4.z; v[j + 3] = t4.w;
    }

    // zero parity-0 buffers (p_0 = 0) for both chains
    for (int i = tid; i < 2 * CL * RANK; i += 256) {
        int ch = i / (CL * RANK), rest = i % (CL * RANK);
        pbuf[ch][0][rest / RANK][rest % RANK] = 0.0f;
    }

    const uint32_t mbar0 = smem_u32(&mbar[0]);
    if (tid == 0) {
        asm volatile("mbarrier.init.shared.b64 [%0], %1;"
                     :: "r"(mbar0), "r"((unsigned)CL) : "memory");
        asm volatile("mbarrier.init.shared.b64 [%0], %1;"
                     :: "r"(mbar0 + 8), "r"((unsigned)CL) : "memory");
    }

    uint32_t mybuf = smem_u32(&pbuf[0][0][0][0]);
    uint32_t peerbuf[CL], peerbar[CL];
#pragma unroll
    for (int k = 0; k < CL; k++) {
        asm("mapa.shared::cluster.u32 %0, %1, %2;"
            : "=r"(peerbuf[k]) : "r"(mybuf), "r"(k));
        asm("mapa.shared::cluster.u32 %0, %1, %2;"
            : "=r"(peerbar[k]) : "r"(mbar0), "r"(k));
    }
    __syncthreads();
    asm volatile("barrier.cluster.arrive.aligned;" ::: "memory");
    asm volatile("barrier.cluster.wait.aligned;" ::: "memory");

    // preload c for t = 1 (chain A = batch b0, chain B = batch b0+1)
    float cA = hidden[(size_t)b0 * DH + col];
    float cB = hidden[(size_t)(b0 + 1) * DH + col];

    for (int t = 1; t <= T_STEPS; ++t) {
        float* row = hidden + (size_t)(t - 1) * BATCH * DH;
        const float* rowN = hidden + (size_t)t * BATCH * DH;
        const int par  = (t - 1) & 1;
        const int wpar = t & 1;

#pragma unroll
        for (int ch = 0; ch < 2; ++ch) {
            const int b = b0 + ch;
            float cc = ch ? cB : cA;

            // ---- wait for this chain's p_{t-1} partials ----
            if (t >= 2) {
                mbar_wait(mbar0 + ch * 8, (unsigned)(t & 1));
                if (tid == 0)
                    asm volatile("fence.acq_rel.cluster;" ::: "memory");
                __syncthreads();
            }

            // ---- fold 4 rank-partials ----
            if (tid < RANK)
                pcur[ch][tid] = pbuf[ch][par][0][tid] + pbuf[ch][par][1][tid]
                              + pbuf[ch][par][2][tid] + pbuf[ch][par][3][tid];
            __syncthreads();

            // ---- phase ii: g = c + u . p ; h = relu(g) ----
            float g = cc;
            const float4* p4 = (const float4*)pcur[ch];
#pragma unroll
            for (int r4 = 0; r4 < 16; ++r4) {
                float4 pv = p4[r4];              // broadcast LDS
                g += u[4 * r4 + 0] * pv.x;
                g += u[4 * r4 + 1] * pv.y;
                g += u[4 * r4 + 2] * pv.z;
                g += u[4 * r4 + 3] * pv.w;
            }
            float h = fmaxf(g, 0.0f);
            row[(size_t)b * DH + col] = h;       // in-place: c -> h
            sH[ch][tid] = h;

            // prefetch c for step t+1 (long latency cover)
            if (t < T_STEPS) {
                float cn = rowN[(size_t)b * DH + col];
                if (ch) cB = cn; else cA = cn;
            }

            // group barrier: phase iii of group qq reads only sH cols written
            // by this same 64-thread group (warps 2qq, 2qq+1)
            asm volatile("bar.sync %0, 64;" :: "r"(1 + qq) : "memory");

            // ---- phase iii: partial p over this thread's 64-col chunk ----
            float a = 0.0f;
            const float4* hq = (const float4*)&sH[ch][qq * 64];
#pragma unroll
            for (int j4 = 0; j4 < 16; ++j4) {
                float4 hv = hq[j4];              // broadcast LDS
                a += v[4 * j4 + 0] * hv.x;
                a += v[4 * j4 + 1] * hv.y;
                a += v[4 * j4 + 2] * hv.z;
                a += v[4 * j4 + 3] * hv.w;
            }
            sTmp[ch][qq][rr] = a;
            __syncthreads();

            // ---- fold q-chunks + scatter to 4 cluster CTAs via DSMEM ----
            if (tid < RANK) {
                float s = sTmp[ch][0][tid] + sTmp[ch][1][tid]
                        + sTmp[ch][2][tid] + sTmp[ch][3][tid];
                uint32_t off =
                    (uint32_t)((((ch * 2 + wpar) * CL + rank) * RANK) + tid) * 4u;
#pragma unroll
                for (int k = 0; k < CL; k++)
                    asm volatile("st.shared::cluster.f32 [%0], %1;"
                                 :: "r"(peerbuf[k] + off), "f"(s) : "memory");
            }
            __syncthreads();
            if (tid == 0) {
                asm volatile("fence.acq_rel.cluster;" ::: "memory");
#pragma unroll
                for (int k = 0; k < CL; k++)
                    asm volatile("mbarrier.arrive.shared::cluster.b64 _, [%0];"
                                 :: "r"(peerbar[k] + ch * 8) : "memory");
            }
        }
    }

    asm volatile("barrier.cluster.arrive.aligned;" ::: "memory");
    asm volatile("barrier.cluster.wait.aligned;" ::: "memory");
}

// ---------------- launch -----------------------------------------------------
extern "C" void kernel_launch(void* const* d_in, const int* in_sizes, int n_in,
                              void* d_out, int out_size) {
    (void)in_sizes; (void)n_in; (void)out_size;
    const float* x  = (const float*)d_in[0];
    const float* Wi = (const float*)d_in[1];
    const float* U  = (const float*)d_in[2];
    const float* V  = (const float*)d_in[3];
    const float* bh = (const float*)d_in[4];
    const float* Wo = (const float*)d_in[5];
    const float* bo = (const float*)d_in[6];

    float* hidden = (float*)d_out;                                   // [T,B,DH]
    float* outp   = hidden + (size_t)T_STEPS * BATCH * DH;           // [T,B,DOUT]

    // c = x @ Wi^T + bh  (written into hidden region, consumed in place)
    dim3 gA(T_STEPS * BATCH / 64, DH / 64);
    gemm_bt<<<gA, 256>>>(x, Wi, bh, hidden, DH, DIN);

    // serial recurrence: 32 clusters x 4 CTAs, dual interleaved batch chains
    rnn_recur<<<BATCH / BGRP * CL, 256>>>(U, V, hidden);

    // output = hidden @ Wo^T + bo
    dim3 gC(T_STEPS * BATCH / 64, DOUT / 64);
    gemm_bt<<<gC, 256>>>(hidden, Wo, bo, outp, DOUT, DH);
}

// round 12
// speedup vs baseline: 1.4735x; 1.4735x over previous
#include <cuda_runtime.h>
#include <cstdint>

#define T_STEPS 512
#define BATCH   64
#define DIN     128
#define DH      1024
#define DOUT    256
#define RANK    64

#define CL      4            // cluster size (CTAs per batch-pair)
#define COLS    256          // DH / CL columns per CTA
#define BGRP    2            // batch elements per cluster
// recurrence grid = 128 CTAs = 32 clusters * 4; one wave on 148 SMs

// ---------------- C[m,n] = bias[n] + sum_k A[m,k]*B[n,k] --------------------
// A: [M,K] row-major, B: [N,K] row-major (B^T GEMM).
// 128x128 tile, BK=16, 8x8 microtile, 256 threads.
#define BM 128
#define BN 128
#define BK 16

__global__ void __launch_bounds__(256) gemm_bt(const float* __restrict__ A,
                                               const float* __restrict__ Bm,
                                               const float* __restrict__ bias,
                                               float* __restrict__ C,
                                               int N, int K) {
    __shared__ float sA[BK][BM + 4];   // k-major; stride 132 (16B-aligned rows)
    __shared__ float sB[BK][BN + 4];
    const int tid = threadIdx.x;
    const int m0 = blockIdx.x * BM;
    const int n0 = blockIdx.y * BN;
    const int tx = tid & 15;           // n micro-tile 0..15
    const int ty = tid >> 4;           // m micro-tile 0..15
    const int lrow = tid >> 1;         // 0..127 (load row)
    const int lkk  = (tid & 1) * 8;    // 0 or 8 (k-offset, 8 floats)

    float acc[8][8];
#pragma unroll
    for (int i = 0; i < 8; i++)
#pragma unroll
        for (int j = 0; j < 8; j++) acc[i][j] = 0.0f;

    for (int k0 = 0; k0 < K; k0 += BK) {
        const float* ap = A + (size_t)(m0 + lrow) * K + k0 + lkk;
        const float* bp = Bm + (size_t)(n0 + lrow) * K + k0 + lkk;
        float4 a0 = *(const float4*)ap;
        float4 a1 = *(const float4*)(ap + 4);
        float4 b0 = *(const float4*)bp;
        float4 b1 = *(const float4*)(bp + 4);
        sA[lkk + 0][lrow] = a0.x; sA[lkk + 1][lrow] = a0.y;
        sA[lkk + 2][lrow] = a0.z; sA[lkk + 3][lrow] = a0.w;
        sA[lkk + 4][lrow] = a1.x; sA[lkk + 5][lrow] = a1.y;
        sA[lkk + 6][lrow] = a1.z; sA[lkk + 7][lrow] = a1.w;
        sB[lkk + 0][lrow] = b0.x; sB[lkk + 1][lrow] = b0.y;
        sB[lkk + 2][lrow] = b0.z; sB[lkk + 3][lrow] = b0.w;
        sB[lkk + 4][lrow] = b1.x; sB[lkk + 5][lrow] = b1.y;
        sB[lkk + 6][lrow] = b1.z; sB[lkk + 7][lrow] = b1.w;
        __syncthreads();
#pragma unroll
        for (int k = 0; k < BK; k++) {
            float4 a01 = *(const float4*)&sA[k][ty * 8];
            float4 a23 = *(const float4*)&sA[k][ty * 8 + 4];
            float4 b01 = *(const float4*)&sB[k][tx * 8];
            float4 b23 = *(const float4*)&sB[k][tx * 8 + 4];
            float a[8] = {a01.x, a01.y, a01.z, a01.w, a23.x, a23.y, a23.z, a23.w};
            float b[8] = {b01.x, b01.y, b01.z, b01.w, b23.x, b23.y, b23.z, b23.w};
#pragma unroll
            for (int i = 0; i < 8; i++)
#pragma unroll
                for (int j = 0; j < 8; j++) acc[i][j] += a[i] * b[j];
        }
        __syncthreads();
    }

    float4 bs0 = *(const float4*)&bias[n0 + tx * 8];
    float4 bs1 = *(const float4*)&bias[n0 + tx * 8 + 4];
    float bb[8] = {bs0.x, bs0.y, bs0.z, bs0.w, bs1.x, bs1.y, bs1.z, bs1.w};
#pragma unroll
    for (int i = 0; i < 8; i++) {
        float* crow = C + (size_t)(m0 + ty * 8 + i) * N + n0 + tx * 8;
        float4 o0, o1;
        o0.x = acc[i][0] + bb[0]; o0.y = acc[i][1] + bb[1];
        o0.z = acc[i][2] + bb[2]; o0.w = acc[i][3] + bb[3];
        o1.x = acc[i][4] + bb[4]; o1.y = acc[i][5] + bb[5];
        o1.z = acc[i][6] + bb[6]; o1.w = acc[i][7] + bb[7];
        *(float4*)crow = o0;
        *(float4*)(crow + 4) = o1;
    }
}

// ---------------- clustered recurrence (R8 proven version) -------------------
__device__ __forceinline__ uint32_t smem_u32(const void* p) {
    uint32_t a;
    asm("{ .reg .u64 t; cvta.to.shared.u64 t, %1; cvt.u32.u64 %0, t; }"
        : "=r"(a) : "l"(p));
    return a;
}

__device__ __forceinline__ void mbar_wait(uint32_t mbar, uint32_t parity) {
    asm volatile(
        "{\n\t"
        ".reg .pred P;\n\t"
        "W%=:\n\t"
        "mbarrier.try_wait.parity.acquire.cta.shared::cta.b64 P, [%0], %1, 0x989680;\n\t"
        "@P bra D%=;\n\t"
        "bra W%=;\n\t"
        "D%=:\n\t"
        "}"
        :: "r"(mbar), "r"(parity) : "memory");
}

__global__ void __launch_bounds__(256, 1) __cluster_dims__(CL, 1, 1)
rnn_recur(const float* __restrict__ U, const float* __restrict__ V,
          float* __restrict__ hidden) {
    __shared__ __align__(16) float pbuf[2][CL][BGRP][RANK];
    __shared__ __align__(16) float pcur[BGRP][RANK];
    __shared__ __align__(16) float sH[BGRP][COLS];
    __shared__ __align__(16) float sTmp[CL][BGRP][RANK];
    __shared__ __align__(8) unsigned long long mbar;

    const int tid  = threadIdx.x;
    const int rank = blockIdx.x & (CL - 1);
    const int clus = blockIdx.x >> 2;
    const int b0   = clus * BGRP;
    const int colbase = rank * COLS;
    const int col  = colbase + tid;

    const int rr = tid & 63;                    // phase iii: rank index
    const int qq = tid >> 6;                    // phase iii: 64-col chunk

    // ---- persistent register weights ----
    float u[RANK];
#pragma unroll
    for (int r = 0; r < RANK; r += 4) {
        float4 t4 = *(const float4*)&U[(size_t)col * RANK + r];
        u[r] = t4.x; u[r + 1] = t4.y; u[r + 2] = t4.z; u[r + 3] = t4.w;
    }
    float v[64];
#pragma unroll
    for (int j = 0; j < 64; j += 4) {
        float4 t4 = *(const float4*)&V[(size_t)rr * DH + colbase + qq * 64 + j];
        v[j] = t4.x; v[j + 1] = t4.y; v[j + 2] = t4.z; v[j + 3] = t4.w;
    }

    // zero parity-0 buffer (p_0 = 0)
    for (int i = tid; i < CL * BGRP * RANK; i += 256)
        (&pbuf[0][0][0][0])[i] = 0.0f;

    const uint32_t mymbar = smem_u32(&mbar);
    if (tid == 0)
        asm volatile("mbarrier.init.shared.b64 [%0], %1;"
                     :: "r"(mymbar), "r"((unsigned)CL) : "memory");

    uint32_t mybuf = smem_u32(&pbuf[0][0][0][0]);
    uint32_t peerbuf[CL], peerbar[CL];
#pragma unroll
    for (int k = 0; k < CL; k++) {
        asm("mapa.shared::cluster.u32 %0, %1, %2;"
            : "=r"(peerbuf[k]) : "r"(mybuf), "r"(k));
        asm("mapa.shared::cluster.u32 %0, %1, %2;"
            : "=r"(peerbar[k]) : "r"(mymbar), "r"(k));
    }
    __syncthreads();
    asm volatile("barrier.cluster.arrive.aligned;" ::: "memory");
    asm volatile("barrier.cluster.wait.aligned;" ::: "memory");

    // preload c for t = 1
    float c0 = hidden[(size_t)b0 * DH + col];
    float c1 = hidden[(size_t)(b0 + 1) * DH + col];

    for (int t = 1; t <= T_STEPS; ++t) {
        float* row = hidden + (size_t)(t - 1) * BATCH * DH;

        if (t >= 2) {
            mbar_wait(mymbar, (unsigned)(t & 1));
            if (tid == 0)
                asm volatile("fence.acq_rel.cluster;" ::: "memory");
            __syncthreads();
        }

        // reduce the 4 rank-partials of p_{t-1}
        const int par = (t - 1) & 1;
        if (tid < BGRP * RANK) {
            int b = tid >> 6, r = tid & 63;
            pcur[b][r] = pbuf[par][0][b][r] + pbuf[par][1][b][r]
                       + pbuf[par][2][b][r] + pbuf[par][3][b][r];
        }
        __syncthreads();

        // ---- phase ii: g = c + u . p ; h = relu(g) ----
        float g0 = c0, g1 = c1;
        const float4* pa4 = (const float4*)pcur[0];
        const float4* pb4 = (const float4*)pcur[1];
#pragma unroll
        for (int r4 = 0; r4 < 16; ++r4) {
            float4 pa = pa4[r4];                 // broadcast LDS
            float4 pb = pb4[r4];
            g0 += u[4 * r4 + 0] * pa.x; g1 += u[4 * r4 + 0] * pb.x;
            g0 += u[4 * r4 + 1] * pa.y; g1 += u[4 * r4 + 1] * pb.y;
            g0 += u[4 * r4 + 2] * pa.z; g1 += u[4 * r4 + 2] * pb.z;
            g0 += u[4 * r4 + 3] * pa.w; g1 += u[4 * r4 + 3] * pb.w;
        }
        float h0 = fmaxf(g0, 0.0f);
        float h1 = fmaxf(g1, 0.0f);
        row[(size_t)b0 * DH + col] = h0;          // in-place: c -> h
        row[(size_t)(b0 + 1) * DH + col] = h1;
        sH[0][tid] = h0;
        sH[1][tid] = h1;

        // prefetch c for step t+1 (consumed next step; long latency cover)
        if (t < T_STEPS) {
            const float* rowN = hidden + (size_t)t * BATCH * DH;
            c0 = rowN[(size_t)b0 * DH + col];
            c1 = rowN[(size_t)(b0 + 1) * DH + col];
        }
        __syncthreads();

        // ---- phase iii: pp[b][rr] partial over this thread's 64-col chunk --
        float a0 = 0.0f, a1 = 0.0f;
        const float4* h0q = (const float4*)&sH[0][qq * 64];  // warp-uniform
        const float4* h1q = (const float4*)&sH[1][qq * 64];
#pragma unroll
        for (int j4 = 0; j4 < 16; ++j4) {
            float4 ha = h0q[j4];                 // broadcast LDS
            float4 hb = h1q[j4];
            a0 += v[4 * j4 + 0] * ha.x; a1 += v[4 * j4 + 0] * hb.x;
            a0 += v[4 * j4 + 1] * ha.y; a1 += v[4 * j4 + 1] * hb.y;
            a0 += v[4 * j4 + 2] * ha.z; a1 += v[4 * j4 + 2] * hb.z;
            a0 += v[4 * j4 + 3] * ha.w; a1 += v[4 * j4 + 3] * hb.w;
        }
        sTmp[qq][0][rr] = a0;
        sTmp[qq][1][rr] = a1;
        __syncthreads();

        // ---- fold q-chunks + scatter to all 4 cluster CTAs via DSMEM -------
        const int wpar = t & 1;
        if (tid < BGRP * RANK) {
            int b = tid >> 6, r = tid & 63;
            float s = sTmp[0][b][r] + sTmp[1][b][r]
                    + sTmp[2][b][r] + sTmp[3][b][r];
            uint32_t off =
                (uint32_t)(((wpar * CL + rank) * BGRP + b) * RANK + r) * 4u;
#pragma unroll
            for (int k = 0; k < CL; k++)
                asm volatile("st.shared::cluster.f32 [%0], %1;"
                             :: "r"(peerbuf[k] + off), "f"(s) : "memory");
        }
        __syncthreads();
        if (tid == 0) {
            asm volatile("fence.acq_rel.cluster;" ::: "memory");
#pragma unroll
            for (int k = 0; k < CL; k++)
                asm volatile("mbarrier.arrive.shared::cluster.b64 _, [%0];"
                             :: "r"(peerbar[k]) : "memory");
        }
    }

    asm volatile("barrier.cluster.arrive.aligned;" ::: "memory");
    asm volatile("barrier.cluster.wait.aligned;" ::: "memory");
}

// ---------------- launch -----------------------------------------------------
extern "C" void kernel_launch(void* const* d_in, const int* in_sizes, int n_in,
                              void* d_out, int out_size) {
    (void)in_sizes; (void)n_in; (void)out_size;
    const float* x  = (const float*)d_in[0];
    const float* Wi = (const float*)d_in[1];
    const float* U  = (const float*)d_in[2];
    const float* V  = (const float*)d_in[3];
    const float* bh = (const float*)d_in[4];
    const float* Wo = (const float*)d_in[5];
    const float* bo = (const float*)d_in[6];

    float* hidden = (float*)d_out;                                   // [T,B,DH]
    float* outp   = hidden + (size_t)T_STEPS * BATCH * DH;           // [T,B,DOUT]

    // c = x @ Wi^T + bh  (written into hidden region, consumed in place)
    dim3 gA(T_STEPS * BATCH / BM, DH / BN);
    gemm_bt<<<gA, 256>>>(x, Wi, bh, hidden, DH, DIN);

    // serial recurrence: 32 clusters x 4 CTAs, DSMEM rank exchange
    rnn_recur<<<BATCH / BGRP * CL, 256>>>(U, V, hidden);

    // output = hidden @ Wo^T + bo
    dim3 gC(T_STEPS * BATCH / BM, DOUT / BN);
    gemm_bt<<<gC, 256>>>(hidden, Wo, bo, outp, DOUT, DH);
}

// round 14
// speedup vs baseline: 1.9254x; 1.3066x over previous
#include <cuda_runtime.h>
#include <cuda_bf16.h>
#include <cstdint>

#define T_STEPS 512
#define BATCH   64
#define DIN     128
#define DH      1024
#define DOUT    256
#define RANK    64

#define CL      4            // cluster size (CTAs per batch-pair)
#define COLS    256          // DH / CL columns per CTA
#define BGRP    2            // batch elements per cluster

// ---------------- bf16x3 split-GEMM via mma.sync (HMMA) ----------------------
// C[m,n] = bias[n] + sum_k A[m,k]*B[n,k],  A:[M,K] row-major, B:[N,K] row-major.
// fp32 operands split in-kernel into bf16 hi+lo; C = Ah*Bh + Ah*Bl + Al*Bh.
// Tile 128x128, K-chunk 32, 8 warps (4m x 2n), warp = 32x64 = 2x8 m16n8k16.
#define KT 32
#define KPAD 40              // bf16 row stride (80 B): conflict-free frag loads

__device__ __forceinline__ void store_split(__nv_bfloat16* hp,
                                            __nv_bfloat16* lp, float4 v) {
    __nv_bfloat16 h0 = __float2bfloat16(v.x);
    __nv_bfloat16 h1 = __float2bfloat16(v.y);
    __nv_bfloat16 h2 = __float2bfloat16(v.z);
    __nv_bfloat16 h3 = __float2bfloat16(v.w);
    __nv_bfloat16 l0 = __float2bfloat16(v.x - __bfloat162float(h0));
    __nv_bfloat16 l1 = __float2bfloat16(v.y - __bfloat162float(h1));
    __nv_bfloat16 l2 = __float2bfloat16(v.z - __bfloat162float(h2));
    __nv_bfloat16 l3 = __float2bfloat16(v.w - __bfloat162float(h3));
    uint2 uh, ul;
    uh.x = ((uint32_t)__bfloat16_as_ushort(h1) << 16) | __bfloat16_as_ushort(h0);
    uh.y = ((uint32_t)__bfloat16_as_ushort(h3) << 16) | __bfloat16_as_ushort(h2);
    ul.x = ((uint32_t)__bfloat16_as_ushort(l1) << 16) | __bfloat16_as_ushort(l0);
    ul.y = ((uint32_t)__bfloat16_as_ushort(l3) << 16) | __bfloat16_as_ushort(l2);
    *(uint2*)hp = uh;
    *(uint2*)lp = ul;
}

__device__ __forceinline__ void mma16816(float* c, const uint32_t* a,
                                         const uint32_t* b) {
    asm volatile(
        "mma.sync.aligned.m16n8k16.row.col.f32.bf16.bf16.f32 "
        "{%0,%1,%2,%3}, {%4,%5,%6,%7}, {%8,%9}, {%0,%1,%2,%3};"
        : "+f"(c[0]), "+f"(c[1]), "+f"(c[2]), "+f"(c[3])
        : "r"(a[0]), "r"(a[1]), "r"(a[2]), "r"(a[3]), "r"(b[0]), "r"(b[1]));
}

__global__ void __launch_bounds__(256) mma_bt(const float* __restrict__ A,
                                              const float* __restrict__ Bm,
                                              const float* __restrict__ bias,
                                              float* __restrict__ C,
                                              int N, int K) {
    __shared__ __nv_bfloat16 sAh[128][KPAD], sAl[128][KPAD];
    __shared__ __nv_bfloat16 sBh[128][KPAD], sBl[128][KPAD];

    const int tid  = threadIdx.x;
    const int lane = tid & 31;
    const int w    = tid >> 5;
    const int wm   = w & 3;            // warp m 0..3 (32 rows each)
    const int wn   = w >> 2;           // warp n 0..1 (64 cols each)
    const int m0 = blockIdx.x * 128;
    const int n0 = blockIdx.y * 128;

    const int lrow = tid >> 1;         // loader row 0..127
    const int lk   = (tid & 1) * 16;   // loader k offset

    float acc[2][8][4];
#pragma unroll
    for (int mi = 0; mi < 2; mi++)
#pragma unroll
        for (int ni = 0; ni < 8; ni++)
#pragma unroll
            for (int q = 0; q < 4; q++) acc[mi][ni][q] = 0.0f;

    const int fr = lane >> 2;          // fragment row (0..7)
    const int fc = (lane & 3) * 2;     // fragment k-col base

#pragma unroll 1
    for (int kc = 0; kc < K; kc += KT) {
        // ---- load fp32, split to bf16 hi/lo, store to SMEM ----
        const float* ap = A + (size_t)(m0 + lrow) * K + kc + lk;
        const float* bp = Bm + (size_t)(n0 + lrow) * K + kc + lk;
#pragma unroll
        for (int j = 0; j < 4; j++) {
            float4 av = *(const float4*)(ap + 4 * j);
            float4 bv = *(const float4*)(bp + 4 * j);
            store_split(&sAh[lrow][lk + 4 * j], &sAl[lrow][lk + 4 * j], av);
            store_split(&sBh[lrow][lk + 4 * j], &sBl[lrow][lk + 4 * j], bv);
        }
        __syncthreads();

        // ---- 2 k16 steps, 2x8 tiles, 3 products each ----
#pragma unroll
        for (int ks = 0; ks < 2; ks++) {
            const int c = ks * 16 + fc;
            uint32_t ah[2][4], al[2][4], bh[8][2], bl[8][2];
#pragma unroll
            for (int mi = 0; mi < 2; mi++) {
                const int r = wm * 32 + mi * 16 + fr;
                ah[mi][0] = *(const uint32_t*)&sAh[r][c];
                ah[mi][1] = *(const uint32_t*)&sAh[r + 8][c];
                ah[mi][2] = *(const uint32_t*)&sAh[r][c + 8];
                ah[mi][3] = *(const uint32_t*)&sAh[r + 8][c + 8];
                al[mi][0] = *(const uint32_t*)&sAl[r][c];
                al[mi][1] = *(const uint32_t*)&sAl[r + 8][c];
                al[mi][2] = *(const uint32_t*)&sAl[r][c + 8];
                al[mi][3] = *(const uint32_t*)&sAl[r + 8][c + 8];
            }
#pragma unroll
            for (int ni = 0; ni < 8; ni++) {
                const int nn = wn * 64 + ni * 8 + fr;
                bh[ni][0] = *(const uint32_t*)&sBh[nn][c];
                bh[ni][1] = *(const uint32_t*)&sBh[nn][c + 8];
                bl[ni][0] = *(const uint32_t*)&sBl[nn][c];
                bl[ni][1] = *(const uint32_t*)&sBl[nn][c + 8];
            }
#pragma unroll
            for (int mi = 0; mi < 2; mi++)
#pragma unroll
                for (int ni = 0; ni < 8; ni++) {
                    mma16816(acc[mi][ni], ah[mi], bh[ni]);
                    mma16816(acc[mi][ni], ah[mi], bl[ni]);
                    mma16816(acc[mi][ni], al[mi], bh[ni]);
                }
        }
        __syncthreads();
    }

    // ---- epilogue: bias + store ----
#pragma unroll
    for (int mi = 0; mi < 2; mi++) {
        const int r0 = m0 + wm * 32 + mi * 16 + fr;
#pragma unroll
        for (int ni = 0; ni < 8; ni++) {
            const int col = n0 + wn * 64 + ni * 8 + (lane & 3) * 2;
            const float b0v = bias[col];
            const float b1v = bias[col + 1];
            float2 o0 = make_float2(acc[mi][ni][0] + b0v, acc[mi][ni][1] + b1v);
            float2 o1 = make_float2(acc[mi][ni][2] + b0v, acc[mi][ni][3] + b1v);
            *(float2*)&C[(size_t)r0 * N + col] = o0;
            *(float2*)&C[(size_t)(r0 + 8) * N + col] = o1;
        }
    }
}

// ---------------- common PTX helpers ----------------------------------------
__device__ __forceinline__ uint32_t smem_u32(const void* p) {
    uint32_t a;
    asm("{ .reg .u64 t; cvta.to.shared.u64 t, %1; cvt.u32.u64 %0, t; }"
        : "=r"(a) : "l"(p));
    return a;
}

__device__ __forceinline__ void mbar_wait(uint32_t mbar, uint32_t parity) {
    asm volatile(
        "{\n\t"
        ".reg .pred P;\n\t"
        "W%=:\n\t"
        "mbarrier.try_wait.parity.acquire.cta.shared::cta.b64 P, [%0], %1, 0x989680;\n\t"
        "@P bra D%=;\n\t"
        "bra W%=;\n\t"
        "D%=:\n\t"
        "}"
        :: "r"(mbar), "r"(parity) : "memory");
}

// ---------------- clustered recurrence (R8/R12 proven version) ---------------
__global__ void __launch_bounds__(256, 1) __cluster_dims__(CL, 1, 1)
rnn_recur(const float* __restrict__ U, const float* __restrict__ V,
          float* __restrict__ hidden) {
    __shared__ __align__(16) float pbuf[2][CL][BGRP][RANK];
    __shared__ __align__(16) float pcur[BGRP][RANK];
    __shared__ __align__(16) float sH[BGRP][COLS];
    __shared__ __align__(16) float sTmp[CL][BGRP][RANK];
    __shared__ __align__(8) unsigned long long mbar;

    const int tid  = threadIdx.x;
    const int rank = blockIdx.x & (CL - 1);
    const int clus = blockIdx.x >> 2;
    const int b0   = clus * BGRP;
    const int colbase = rank * COLS;
    const int col  = colbase + tid;

    const int rr = tid & 63;
    const int qq = tid >> 6;

    float u[RANK];
#pragma unroll
    for (int r = 0; r < RANK; r += 4) {
        float4 t4 = *(const float4*)&U[(size_t)col * RANK + r];
        u[r] = t4.x; u[r + 1] = t4.y; u[r + 2] = t4.z; u[r + 3] = t4.w;
    }
    float v[64];
#pragma unroll
    for (int j = 0; j < 64; j += 4) {
        float4 t4 = *(const float4*)&V[(size_t)rr * DH + colbase + qq * 64 + j];
        v[j] = t4.x; v[j + 1] = t4.y; v[j + 2] = t4.z; v[j + 3] = t4.w;
    }

    for (int i = tid; i < CL * BGRP * RANK; i += 256)
        (&pbuf[0][0][0][0])[i] = 0.0f;

    const uint32_t mymbar = smem_u32(&mbar);
    if (tid == 0)
        asm volatile("mbarrier.init.shared.b64 [%0], %1;"
                     :: "r"(mymbar), "r"((unsigned)CL) : "memory");

    uint32_t mybuf = smem_u32(&pbuf[0][0][0][0]);
    uint32_t peerbuf[CL], peerbar[CL];
#pragma unroll
    for (int k = 0; k < CL; k++) {
        asm("mapa.shared::cluster.u32 %0, %1, %2;"
            : "=r"(peerbuf[k]) : "r"(mybuf), "r"(k));
        asm("mapa.shared::cluster.u32 %0, %1, %2;"
            : "=r"(peerbar[k]) : "r"(mymbar), "r"(k));
    }
    __syncthreads();
    asm volatile("barrier.cluster.arrive.aligned;" ::: "memory");
    asm volatile("barrier.cluster.wait.aligned;" ::: "memory");

    float c0 = hidden[(size_t)b0 * DH + col];
    float c1 = hidden[(size_t)(b0 + 1) * DH + col];

    for (int t = 1; t <= T_STEPS; ++t) {
        float* row = hidden + (size_t)(t - 1) * BATCH * DH;

        if (t >= 2) {
            mbar_wait(mymbar, (unsigned)(t & 1));
            if (tid == 0)
                asm volatile("fence.acq_rel.cluster;" ::: "memory");
            __syncthreads();
        }

        const int par = (t - 1) & 1;
        if (tid < BGRP * RANK) {
            int b = tid >> 6, r = tid & 63;
            pcur[b][r] = pbuf[par][0][b][r] + pbuf[par][1][b][r]
                       + pbuf[par][2][b][r] + pbuf[par][3][b][r];
        }
        __syncthreads();

        float g0 = c0, g1 = c1;
        const float4* pa4 = (const float4*)pcur[0];
        const float4* pb4 = (const float4*)pcur[1];
#pragma unroll
        for (int r4 = 0; r4 < 16; ++r4) {
            float4 pa = pa4[r4];
            float4 pb = pb4[r4];
            g0 += u[4 * r4 + 0] * pa.x; g1 += u[4 * r4 + 0] * pb.x;
            g0 += u[4 * r4 + 1] * pa.y; g1 += u[4 * r4 + 1] * pb.y;
            g0 += u[4 * r4 + 2] * pa.z; g1 += u[4 * r4 + 2] * pb.z;
            g0 += u[4 * r4 + 3] * pa.w; g1 += u[4 * r4 + 3] * pb.w;
        }
        float h0 = fmaxf(g0, 0.0f);
        float h1 = fmaxf(g1, 0.0f);
        row[(size_t)b0 * DH + col] = h0;
        row[(size_t)(b0 + 1) * DH + col] = h1;
        sH[0][tid] = h0;
        sH[1][tid] = h1;

        if (t < T_STEPS) {
            const float* rowN = hidden + (size_t)t * BATCH * DH;
            c0 = rowN[(size_t)b0 * DH + col];
            c1 = rowN[(size_t)(b0 + 1) * DH + col];
        }
        __syncthreads();

        float a0 = 0.0f, a1 = 0.0f;
        const float4* h0q = (const float4*)&sH[0][qq * 64];
        const float4* h1q = (const float4*)&sH[1][qq * 64];
#pragma unroll
        for (int j4 = 0; j4 < 16; ++j4) {
            float4 ha = h0q[j4];
            float4 hb = h1q[j4];
            a0 += v[4 * j4 + 0] * ha.x; a1 += v[4 * j4 + 0] * hb.x;
            a0 += v[4 * j4 + 1] * ha.y; a1 += v[4 * j4 + 1] * hb.y;
            a0 += v[4 * j4 + 2] * ha.z; a1 += v[4 * j4 + 2] * hb.z;
            a0 += v[4 * j4 + 3] * ha.w; a1 += v[4 * j4 + 3] * hb.w;
        }
        sTmp[qq][0][rr] = a0;
        sTmp[qq][1][rr] = a1;
        __syncthreads();

        const int wpar = t & 1;
        if (tid < BGRP * RANK) {
            int b = tid >> 6, r = tid & 63;
            float s = sTmp[0][b][r] + sTmp[1][b][r]
                    + sTmp[2][b][r] + sTmp[3][b][r];
            uint32_t off =
                (uint32_t)(((wpar * CL + rank) * BGRP + b) * RANK + r) * 4u;
#pragma unroll
            for (int k = 0; k < CL; k++)
                asm volatile("st.shared::cluster.f32 [%0], %1;"
                             :: "r"(peerbuf[k] + off), "f"(s) : "memory");
        }
        __syncthreads();
        if (tid == 0) {
            asm volatile("fence.acq_rel.cluster;" ::: "memory");
#pragma unroll
            for (int k = 0; k < CL; k++)
                asm volatile("mbarrier.arrive.shared::cluster.b64 _, [%0];"
                             :: "r"(peerbar[k]) : "memory");
        }
    }

    asm volatile("barrier.cluster.arrive.aligned;" ::: "memory");
    asm volatile("barrier.cluster.wait.aligned;" ::: "memory");
}

// ---------------- launch -----------------------------------------------------
extern "C" void kernel_launch(void* const* d_in, const int* in_sizes, int n_in,
                              void* d_out, int out_size) {
    (void)in_sizes; (void)n_in; (void)out_size;
    const float* x  = (const float*)d_in[0];
    const float* Wi = (const float*)d_in[1];
    const float* U  = (const float*)d_in[2];
    const float* V  = (const float*)d_in[3];
    const float* bh = (const float*)d_in[4];
    const float* Wo = (const float*)d_in[5];
    const float* bo = (const float*)d_in[6];

    float* hidden = (float*)d_out;                                   // [T,B,DH]
    float* outp   = hidden + (size_t)T_STEPS * BATCH * DH;           // [T,B,DOUT]

    // c = x @ Wi^T + bh  (bf16x3 HMMA; written into hidden region)
    dim3 gA(T_STEPS * BATCH / 128, DH / 128);
    mma_bt<<<gA, 256>>>(x, Wi, bh, hidden, DH, DIN);

    // serial recurrence: 32 clusters x 4 CTAs, DSMEM rank exchange
    rnn_recur<<<BATCH / BGRP * CL, 256>>>(U, V, hidden);

    // output = hidden @ Wo^T + bo  (bf16x3 HMMA)
    dim3 gC(T_STEPS * BATCH / 128, DOUT / 128);
    mma_bt<<<gC, 256>>>(hidden, Wo, bo, outp, DOUT, DH);
}